// round 5
// baseline (speedup 1.0000x reference)
#include <cuda_runtime.h>
#include <math.h>

// Problem constants
#define Bb 2
#define Nn 2048
#define Cc 1024
#define Hh 16
#define HDIM 64
#define ATT_SCALE 0.125f   // 64^-0.5

// Scratch (device globals — no allocation allowed in kernel_launch)
__device__ float g_qkv[(size_t)Bb * Nn * 3 * Cc];  // [B, N, 3C] ; 3C split = (3, H, HD)
__device__ float g_att[(size_t)Bb * Nn * Cc];      // [B, N, C]  attention output pre-proj

// ---------------------------------------------------------------------------
// SGEMM with bias: C[M,N] = A[M,K] @ B[K,N] + bias[N]
// fp32, 128x128x16 tiles, 256 threads, 8x8 micro-tile per thread, float4
// global + shared accesses, DOUBLE-BUFFERED smem (one __syncthreads per
// k-tile; next tile's global loads issued before compute on current tile).
// ---------------------------------------------------------------------------
template<int BM, int BN, int BK, int TM, int TN>
__global__ __launch_bounds__(256)
void sgemm_bias_kernel(const float* __restrict__ A,
                       const float* __restrict__ Bm,
                       const float* __restrict__ bias,
                       float* __restrict__ C,
                       int M, int N, int K)
{
    __shared__ float As[2][BK][BM];   // A tile transposed: As[buf][k][m]
    __shared__ float Bs[2][BK][BN];   // Bs[buf][k][n]

    const int tid = threadIdx.x;
    const int bx = blockIdx.x;        // along N
    const int by = blockIdx.y;        // along M
    const int tx = tid % (BN / TN);   // 0..15
    const int ty = tid / (BN / TN);   // 0..15

    const float* Ablk = A + (size_t)by * BM * K;
    const float* Bblk = Bm + (size_t)bx * BN;

    // Load mapping (256 threads, BK=16):
    // A tile: BM*BK = 2048 floats = 512 float4 -> 2 float4/thread.
    //   load L covers rows [L*64, L*64+63]; a_col spans 16 along K.
    const int a_row = tid / (BK / 4);        // 0..63
    const int a_col = (tid % (BK / 4)) * 4;  // 0,4,8,12
    // B tile: BK*BN = 2048 floats = 512 float4 -> 2 float4/thread.
    //   load L covers rows [L*8, L*8+7]; warp covers 512B contiguous in a row.
    const int b_row = tid / (BN / 4);        // 0..7
    const int b_col = (tid % (BN / 4)) * 4;  // 0..124

    float acc[TM][TN];
    #pragma unroll
    for (int i = 0; i < TM; i++)
        #pragma unroll
        for (int j = 0; j < TN; j++) acc[i][j] = 0.f;

    // --- prologue: load tile 0 into buffer 0 ---
    {
        #pragma unroll
        for (int L = 0; L < 2; L++) {
            const int r = a_row + L * (BM / 2);
            float4 av = *(const float4*)(Ablk + (size_t)r * K + a_col);
            As[0][a_col + 0][r] = av.x;
            As[0][a_col + 1][r] = av.y;
            As[0][a_col + 2][r] = av.z;
            As[0][a_col + 3][r] = av.w;
        }
        #pragma unroll
        for (int L = 0; L < 2; L++) {
            const int r = b_row + L * (BK / 2);
            float4 bv = *(const float4*)(Bblk + (size_t)r * N + b_col);
            *(float4*)&Bs[0][r][b_col] = bv;
        }
    }
    __syncthreads();

    int buf = 0;
    for (int k0 = 0; k0 < K; k0 += BK) {
        // Prefetch next tile from global into registers (latency overlapped
        // with the FFMA mainloop below).
        float4 av_n[2], bv_n[2];
        const bool has_next = (k0 + BK) < K;
        if (has_next) {
            #pragma unroll
            for (int L = 0; L < 2; L++) {
                const int r = a_row + L * (BM / 2);
                av_n[L] = *(const float4*)(Ablk + (size_t)r * K + k0 + BK + a_col);
            }
            #pragma unroll
            for (int L = 0; L < 2; L++) {
                const int r = b_row + L * (BK / 2);
                bv_n[L] = *(const float4*)(Bblk + (size_t)(k0 + BK + r) * N + b_col);
            }
        }

        #pragma unroll
        for (int kk = 0; kk < BK; kk++) {
            float areg[TM], breg[TN];
            float4 a0 = *(const float4*)&As[buf][kk][ty * TM];
            float4 a1 = *(const float4*)&As[buf][kk][ty * TM + 4];
            areg[0]=a0.x; areg[1]=a0.y; areg[2]=a0.z; areg[3]=a0.w;
            areg[4]=a1.x; areg[5]=a1.y; areg[6]=a1.z; areg[7]=a1.w;
            float4 b0 = *(const float4*)&Bs[buf][kk][tx * TN];
            float4 b1 = *(const float4*)&Bs[buf][kk][tx * TN + 4];
            breg[0]=b0.x; breg[1]=b0.y; breg[2]=b0.z; breg[3]=b0.w;
            breg[4]=b1.x; breg[5]=b1.y; breg[6]=b1.z; breg[7]=b1.w;
            #pragma unroll
            for (int i = 0; i < TM; i++)
                #pragma unroll
                for (int j = 0; j < TN; j++)
                    acc[i][j] += areg[i] * breg[j];
        }

        if (has_next) {
            const int nbuf = buf ^ 1;
            #pragma unroll
            for (int L = 0; L < 2; L++) {
                const int r = a_row + L * (BM / 2);
                As[nbuf][a_col + 0][r] = av_n[L].x;
                As[nbuf][a_col + 1][r] = av_n[L].y;
                As[nbuf][a_col + 2][r] = av_n[L].z;
                As[nbuf][a_col + 3][r] = av_n[L].w;
            }
            #pragma unroll
            for (int L = 0; L < 2; L++) {
                const int r = b_row + L * (BK / 2);
                *(float4*)&Bs[nbuf][r][b_col] = bv_n[L];
            }
            __syncthreads();
            buf = nbuf;
        }
    }

    // Epilogue: add bias, store float4
    #pragma unroll
    for (int i = 0; i < TM; i++) {
        const int row = by * BM + ty * TM + i;
        #pragma unroll
        for (int j = 0; j < TN; j += 4) {
            const int col = bx * BN + tx * TN + j;
            float4 o;
            o.x = acc[i][j + 0] + bias[col + 0];
            o.y = acc[i][j + 1] + bias[col + 1];
            o.z = acc[i][j + 2] + bias[col + 2];
            o.w = acc[i][j + 3] + bias[col + 3];
            *(float4*)(C + (size_t)row * N + col) = o;
        }
    }
}

// ---------------------------------------------------------------------------
// Flash attention fp32. One thread = one query row (online softmax entirely
// in registers — no cross-thread reduction). K/V streamed through smem in
// 64-key tiles; all smem reads are warp-uniform broadcasts (conflict-free).
// qkv layout: [B, N, 3C] with 3C = (part, h, d): q @ h*64+d, k @ C+h*64+d,
// v @ 2C+h*64+d.
// ---------------------------------------------------------------------------
__global__ __launch_bounds__(128)
void attn_kernel(const float* __restrict__ qkv, float* __restrict__ att)
{
    const int bh = blockIdx.y;
    const int b = bh / Hh;
    const int h = bh % Hh;
    const int tid = threadIdx.x;
    const int n = blockIdx.x * 128 + tid;   // this thread's query row

    __shared__ float Ks[64][HDIM];
    __shared__ float Vs[64][HDIM];

    // Load q (pre-scaled) into registers
    const float* qptr = qkv + ((size_t)b * Nn + n) * 3 * Cc + h * HDIM;
    float q[HDIM];
    #pragma unroll
    for (int d = 0; d < HDIM; d += 4) {
        float4 v = *(const float4*)(qptr + d);
        q[d + 0] = v.x * ATT_SCALE;
        q[d + 1] = v.y * ATT_SCALE;
        q[d + 2] = v.z * ATT_SCALE;
        q[d + 3] = v.w * ATT_SCALE;
    }
    float o[HDIM];
    #pragma unroll
    for (int d = 0; d < HDIM; d++) o[d] = 0.f;
    float mmax = -1e30f, lsum = 0.f;

    const float* kbase = qkv + (size_t)b * Nn * 3 * Cc + Cc + h * HDIM;
    const float* vbase = qkv + (size_t)b * Nn * 3 * Cc + 2 * Cc + h * HDIM;

    for (int m0 = 0; m0 < Nn; m0 += 64) {
        __syncthreads();   // previous tile fully consumed
        // 64 rows x 64 floats = 1024 float4; 128 threads -> 8 float4 each
        #pragma unroll
        for (int i = 0; i < 8; i++) {
            int idx = i * 128 + tid;        // 0..1023
            int r = idx >> 4;               // key row in tile
            int c4 = (idx & 15) << 2;       // d offset
            *(float4*)&Ks[r][c4] = *(const float4*)(kbase + (size_t)(m0 + r) * 3 * Cc + c4);
            *(float4*)&Vs[r][c4] = *(const float4*)(vbase + (size_t)(m0 + r) * 3 * Cc + c4);
        }
        __syncthreads();

        #pragma unroll 1
        for (int jc = 0; jc < 64; jc += 16) {
            float s[16];
            #pragma unroll
            for (int j = 0; j < 16; j++) {
                float a0 = 0.f, a1 = 0.f, a2 = 0.f, a3 = 0.f;
                #pragma unroll
                for (int d = 0; d < HDIM; d += 4) {
                    float4 kv = *(const float4*)&Ks[jc + j][d];
                    a0 += q[d + 0] * kv.x;
                    a1 += q[d + 1] * kv.y;
                    a2 += q[d + 2] * kv.z;
                    a3 += q[d + 3] * kv.w;
                }
                s[j] = (a0 + a1) + (a2 + a3);
            }
            float tmax = mmax;
            #pragma unroll
            for (int j = 0; j < 16; j++) tmax = fmaxf(tmax, s[j]);
            const float corr = __expf(mmax - tmax);
            mmax = tmax;
            lsum *= corr;
            #pragma unroll
            for (int d = 0; d < HDIM; d++) o[d] *= corr;
            #pragma unroll
            for (int j = 0; j < 16; j++) {
                const float p = __expf(s[j] - mmax);
                lsum += p;
                #pragma unroll
                for (int d = 0; d < HDIM; d += 4) {
                    float4 vv = *(const float4*)&Vs[jc + j][d];
                    o[d + 0] += p * vv.x;
                    o[d + 1] += p * vv.y;
                    o[d + 2] += p * vv.z;
                    o[d + 3] += p * vv.w;
                }
            }
        }
    }

    const float inv = 1.f / lsum;
    float* optr = att + ((size_t)b * Nn + n) * Cc + h * HDIM;
    #pragma unroll
    for (int d = 0; d < HDIM; d += 4) {
        float4 ov;
        ov.x = o[d + 0] * inv;
        ov.y = o[d + 1] * inv;
        ov.z = o[d + 2] * inv;
        ov.w = o[d + 3] * inv;
        *(float4*)(optr + d) = ov;
    }
}

extern "C" void kernel_launch(void* const* d_in, const int* in_sizes, int n_in,
                              void* d_out, int out_size)
{
    const float* x      = (const float*)d_in[0];  // [B,N,C]
    const float* w_qkv  = (const float*)d_in[1];  // [C,3C]
    const float* b_qkv  = (const float*)d_in[2];  // [3C]
    const float* w_proj = (const float*)d_in[3];  // [C,C]
    const float* b_proj = (const float*)d_in[4];  // [C]
    float* out = (float*)d_out;                   // [B,N,C]

    float* qkv; cudaGetSymbolAddress((void**)&qkv, g_qkv);
    float* att; cudaGetSymbolAddress((void**)&att, g_att);

    constexpr int BM = 128, BN = 128, BK = 16, TM = 8, TN = 8;

    // 1) QKV projection: [4096,1024] @ [1024,3072] + b -> g_qkv
    {
        dim3 grid((3 * Cc) / BN, (Bb * Nn) / BM);
        sgemm_bias_kernel<BM, BN, BK, TM, TN><<<grid, 256>>>(
            x, w_qkv, b_qkv, qkv, Bb * Nn, 3 * Cc, Cc);
    }
    // 2) Attention: g_qkv -> g_att  ([B,N,C], heads interleaved at h*64+d)
    {
        dim3 grid(Nn / 128, Bb * Hh);
        attn_kernel<<<grid, 128>>>(qkv, att);
    }
    // 3) Output projection: [4096,1024] @ [1024,1024] + b -> out
    {
        dim3 grid(Cc / BN, (Bb * Nn) / BM);
        sgemm_bias_kernel<BM, BN, BK, TM, TN><<<grid, 256>>>(
            att, w_proj, b_proj, out, Bb * Nn, Cc, Cc);
    }
}

// round 7
// speedup vs baseline: 1.2805x; 1.2805x over previous
#include <cuda_runtime.h>
#include <cuda_bf16.h>
#include <math.h>
#include <cstdint>

// Problem constants
#define Bb 2
#define Nn 2048
#define Cc 1024
#define Hh 16
#define HDIM 64
#define ATT_SCALE 0.125f   // 64^-0.5
#define MM (Bb*Nn)         // 4096 token rows
#define KK Cc              // 1024
#define NQKV (3*Cc)        // 3072
#define NPROJ Cc           // 1024

// ---------------------------------------------------------------------------
// Device-global scratch (no allocation allowed in kernel_launch)
// ---------------------------------------------------------------------------
__device__ float g_qkv[(size_t)MM * NQKV];   // [tokens, 3C]
__device__ float g_att[(size_t)MM * Cc];     // attention output pre-proj
// bf16 hi/lo split operands
__device__ __nv_bfloat16 g_xhi[(size_t)MM * KK],   g_xlo[(size_t)MM * KK];
__device__ __nv_bfloat16 g_ahi[(size_t)MM * KK],   g_alo[(size_t)MM * KK];
__device__ __nv_bfloat16 g_whi[(size_t)NQKV * KK], g_wlo[(size_t)NQKV * KK];   // wqkv^T [N][K]
__device__ __nv_bfloat16 g_phi[(size_t)NPROJ * KK], g_plo[(size_t)NPROJ * KK]; // wproj^T [N][K]

// ---------------------------------------------------------------------------
// Helpers (baseline PTX only — sm_80+ features, safe for the sm_103 family target)
// ---------------------------------------------------------------------------
__device__ __forceinline__ uint32_t smem_to_u32(const void* smem_ptr) {
    uint32_t addr;
    asm("{ .reg .u64 tmp; cvta.to.shared.u64 tmp, %1; cvt.u32.u64 %0, tmp; }"
        : "=r"(addr) : "l"(smem_ptr));
    return addr;
}

// Swizzled offset inside a [128 rows][32 bf16] tile (row = 64B = 4 x 16B chunks).
// XOR of the 16B-chunk index with (row>>1)&3 makes both the 16B stores and the
// 8-row ldmatrix phases conflict-free (8 addresses distinct mod 128B).
__device__ __forceinline__ uint32_t sw_off(int row, int c16) {
    return (uint32_t)(row * 64) + (uint32_t)(((c16 ^ ((row >> 1) & 3)) & 3) * 16);
}

__device__ __forceinline__ void ldsm_x4(uint32_t& r0, uint32_t& r1, uint32_t& r2,
                                        uint32_t& r3, uint32_t addr) {
    asm volatile("ldmatrix.sync.aligned.m8n8.x4.shared.b16 {%0,%1,%2,%3}, [%4];"
                 : "=r"(r0), "=r"(r1), "=r"(r2), "=r"(r3) : "r"(addr));
}
__device__ __forceinline__ void ldsm_x2(uint32_t& r0, uint32_t& r1, uint32_t addr) {
    asm volatile("ldmatrix.sync.aligned.m8n8.x2.shared.b16 {%0,%1}, [%2];"
                 : "=r"(r0), "=r"(r1) : "r"(addr));
}
__device__ __forceinline__ void mma_bf16(float* c, const uint32_t* a, const uint32_t* b) {
    asm volatile(
        "mma.sync.aligned.m16n8k16.row.col.f32.bf16.bf16.f32 "
        "{%0,%1,%2,%3}, {%4,%5,%6,%7}, {%8,%9}, {%0,%1,%2,%3};"
        : "+f"(c[0]), "+f"(c[1]), "+f"(c[2]), "+f"(c[3])
        : "r"(a[0]), "r"(a[1]), "r"(a[2]), "r"(a[3]), "r"(b[0]), "r"(b[1]));
}

// ---------------------------------------------------------------------------
// Pre-convert: fp32 -> bf16 hi/lo (elementwise, float4)
// ---------------------------------------------------------------------------
__global__ __launch_bounds__(256)
void convert_hilo_kernel(const float* __restrict__ src,
                         __nv_bfloat16* __restrict__ hi,
                         __nv_bfloat16* __restrict__ lo, int n4)
{
    int i = blockIdx.x * 256 + threadIdx.x;
    if (i >= n4) return;
    float4 v = ((const float4*)src)[i];
    __nv_bfloat16 h0 = __float2bfloat16(v.x);
    __nv_bfloat16 h1 = __float2bfloat16(v.y);
    __nv_bfloat16 h2 = __float2bfloat16(v.z);
    __nv_bfloat16 h3 = __float2bfloat16(v.w);
    __nv_bfloat16 l0 = __float2bfloat16(v.x - __bfloat162float(h0));
    __nv_bfloat16 l1 = __float2bfloat16(v.y - __bfloat162float(h1));
    __nv_bfloat16 l2 = __float2bfloat16(v.z - __bfloat162float(h2));
    __nv_bfloat16 l3 = __float2bfloat16(v.w - __bfloat162float(h3));
    ((__nv_bfloat162*)hi)[i*2+0] = __halves2bfloat162(h0, h1);
    ((__nv_bfloat162*)hi)[i*2+1] = __halves2bfloat162(h2, h3);
    ((__nv_bfloat162*)lo)[i*2+0] = __halves2bfloat162(l0, l1);
    ((__nv_bfloat162*)lo)[i*2+1] = __halves2bfloat162(l2, l3);
}

// ---------------------------------------------------------------------------
// Weight transpose + convert: w[K][N] fp32 -> wT_hi/lo [N][K] bf16
// ---------------------------------------------------------------------------
__global__ __launch_bounds__(256)
void transpose_convert_kernel(const float* __restrict__ w,
                              __nv_bfloat16* __restrict__ thi,
                              __nv_bfloat16* __restrict__ tlo,
                              int K, int N)
{
    __shared__ float t[32][33];
    const int k0 = blockIdx.y * 32;
    const int n0 = blockIdx.x * 32;
    const int tx = threadIdx.x;   // 0..31
    const int ty = threadIdx.y;   // 0..7
    #pragma unroll
    for (int i = ty; i < 32; i += 8)
        t[i][tx] = w[(size_t)(k0 + i) * N + n0 + tx];
    __syncthreads();
    #pragma unroll
    for (int i = ty; i < 32; i += 8) {
        float v = t[tx][i];   // w[k0+tx][n0+i]
        __nv_bfloat16 h = __float2bfloat16(v);
        thi[(size_t)(n0 + i) * K + k0 + tx] = h;
        tlo[(size_t)(n0 + i) * K + k0 + tx] = __float2bfloat16(v - __bfloat162float(h));
    }
}

// ---------------------------------------------------------------------------
// HMMA GEMM: C[M,N] = A[M,K] @ B^T[N,K] + bias.  bf16 hi/lo 3-pass, fp32 acc.
// mma.sync m16n8k16 + ldmatrix. CTA 128x128, 8 warps (2x4, warp tile 64x32),
// BK=32 single-buffered smem with register prefetch of the next stage.
// ---------------------------------------------------------------------------
__global__ __launch_bounds__(256)
void hmma_gemm_kernel(const __nv_bfloat16* __restrict__ Ah,
                      const __nv_bfloat16* __restrict__ Al,
                      const __nv_bfloat16* __restrict__ Bh,
                      const __nv_bfloat16* __restrict__ Bl,
                      const float* __restrict__ bias,
                      float* __restrict__ C, int N)
{
    __shared__ __align__(128) char sm[4 * 8192];
    const uint32_t uAh = smem_to_u32(sm);
    const uint32_t uAl = uAh + 8192;
    const uint32_t uBh = uAh + 16384;
    const uint32_t uBl = uAh + 24576;

    const int tid = threadIdx.x;
    const int wid = tid >> 5;
    const int lid = tid & 31;
    const int m0 = blockIdx.y * 128;
    const int n0 = blockIdx.x * 128;
    const int wm = wid >> 2;   // 0..1 -> m offset wm*64
    const int wn = wid & 3;    // 0..3 -> n offset wn*32

    // Global loader mapping: thread t -> row t/2, two 16B chunks at (t&1)*2.
    const int lrow = tid >> 1;
    const int lc   = (tid & 1) * 2;
    const __nv_bfloat16* gAh = Ah + (size_t)(m0 + lrow) * KK + lc * 8;
    const __nv_bfloat16* gAl = Al + (size_t)(m0 + lrow) * KK + lc * 8;
    const __nv_bfloat16* gBh = Bh + (size_t)(n0 + lrow) * KK + lc * 8;
    const __nv_bfloat16* gBl = Bl + (size_t)(n0 + lrow) * KK + lc * 8;
    const uint32_t so0 = sw_off(lrow, lc);
    const uint32_t so1 = sw_off(lrow, lc + 1);

    float acc[4][4][4];
    #pragma unroll
    for (int i = 0; i < 4; i++)
        #pragma unroll
        for (int j = 0; j < 4; j++)
            #pragma unroll
            for (int r = 0; r < 4; r++) acc[i][j][r] = 0.f;

    uint4 pf[8];
    auto LOADG = [&](int s) {
        const size_t o = (size_t)s * 32;
        pf[0] = *(const uint4*)(gAh + o); pf[1] = *(const uint4*)(gAh + o + 8);
        pf[2] = *(const uint4*)(gAl + o); pf[3] = *(const uint4*)(gAl + o + 8);
        pf[4] = *(const uint4*)(gBh + o); pf[5] = *(const uint4*)(gBh + o + 8);
        pf[6] = *(const uint4*)(gBl + o); pf[7] = *(const uint4*)(gBl + o + 8);
    };
    auto STORE = [&]() {
        *(uint4*)(sm + (uAh - smem_to_u32(sm)) + so0) = pf[0];   // == sm + so0
        *(uint4*)(sm + so1) = pf[1];
        *(uint4*)(sm + 8192 + so0) = pf[2];  *(uint4*)(sm + 8192 + so1) = pf[3];
        *(uint4*)(sm + 16384 + so0) = pf[4]; *(uint4*)(sm + 16384 + so1) = pf[5];
        *(uint4*)(sm + 24576 + so0) = pf[6]; *(uint4*)(sm + 24576 + so1) = pf[7];
    };

    // ldmatrix lane-address components (computed once)
    const int a_row_in = (lid & 7) + ((lid >> 3) & 1) * 8;  // row within 16-row m-tile
    const int a_cq     = (lid >> 4);                        // 0/1: low/high k8 of the k16
    const int b_row_in = (lid & 7);
    const int b_cq     = ((lid >> 3) & 1);

    const int NST = KK / 32;
    LOADG(0); STORE();
    __syncthreads();

    for (int s = 0; s < NST; s++) {
        const bool nx = (s + 1) < NST;
        if (nx) LOADG(s + 1);

        #pragma unroll
        for (int ks = 0; ks < 2; ks++) {
            uint32_t ah[4][4], al[4][4], bh[4][2], bl[4][2];
            #pragma unroll
            for (int i = 0; i < 4; i++) {
                const int row = wm * 64 + i * 16 + a_row_in;
                const int c16 = ks * 2 + a_cq;
                ldsm_x4(ah[i][0], ah[i][1], ah[i][2], ah[i][3], uAh + sw_off(row, c16));
                ldsm_x4(al[i][0], al[i][1], al[i][2], al[i][3], uAl + sw_off(row, c16));
            }
            #pragma unroll
            for (int j = 0; j < 4; j++) {
                const int row = wn * 32 + j * 8 + b_row_in;
                const int c16 = ks * 2 + b_cq;
                ldsm_x2(bh[j][0], bh[j][1], uBh + sw_off(row, c16));
                ldsm_x2(bl[j][0], bl[j][1], uBl + sw_off(row, c16));
            }
            #pragma unroll
            for (int i = 0; i < 4; i++)
                #pragma unroll
                for (int j = 0; j < 4; j++)
                    mma_bf16(acc[i][j], ah[i], bh[j]);
            #pragma unroll
            for (int i = 0; i < 4; i++)
                #pragma unroll
                for (int j = 0; j < 4; j++)
                    mma_bf16(acc[i][j], ah[i], bl[j]);
            #pragma unroll
            for (int i = 0; i < 4; i++)
                #pragma unroll
                for (int j = 0; j < 4; j++)
                    mma_bf16(acc[i][j], al[i], bh[j]);
        }

        if (nx) {
            __syncthreads();   // all smem reads of this stage done
            STORE();
            __syncthreads();   // new tiles visible
        }
    }

    // Epilogue: standard m16n8 C layout; add bias; float2 stores (8B aligned).
    #pragma unroll
    for (int i = 0; i < 4; i++) {
        #pragma unroll
        for (int j = 0; j < 4; j++) {
            const int r = m0 + wm * 64 + i * 16 + (lid >> 2);
            const int c = n0 + wn * 32 + j * 8 + (lid & 3) * 2;
            float2 v0, v1;
            v0.x = acc[i][j][0] + bias[c];
            v0.y = acc[i][j][1] + bias[c + 1];
            v1.x = acc[i][j][2] + bias[c];
            v1.y = acc[i][j][3] + bias[c + 1];
            *(float2*)&C[(size_t)r * N + c] = v0;
            *(float2*)&C[(size_t)(r + 8) * N + c] = v1;
        }
    }
}

// ---------------------------------------------------------------------------
// Flash attention fp32 (UNCHANGED from the passing R5 kernel).
// ---------------------------------------------------------------------------
__global__ __launch_bounds__(128)
void attn_kernel(const float* __restrict__ qkv, float* __restrict__ att)
{
    const int bh = blockIdx.y;
    const int b = bh / Hh;
    const int h = bh % Hh;
    const int tid = threadIdx.x;
    const int n = blockIdx.x * 128 + tid;

    __shared__ float Ks[64][HDIM];
    __shared__ float Vs[64][HDIM];

    const float* qptr = qkv + ((size_t)b * Nn + n) * 3 * Cc + h * HDIM;
    float q[HDIM];
    #pragma unroll
    for (int d = 0; d < HDIM; d += 4) {
        float4 v = *(const float4*)(qptr + d);
        q[d + 0] = v.x * ATT_SCALE;
        q[d + 1] = v.y * ATT_SCALE;
        q[d + 2] = v.z * ATT_SCALE;
        q[d + 3] = v.w * ATT_SCALE;
    }
    float o[HDIM];
    #pragma unroll
    for (int d = 0; d < HDIM; d++) o[d] = 0.f;
    float mmax = -1e30f, lsum = 0.f;

    const float* kbase = qkv + (size_t)b * Nn * 3 * Cc + Cc + h * HDIM;
    const float* vbase = qkv + (size_t)b * Nn * 3 * Cc + 2 * Cc + h * HDIM;

    for (int m0 = 0; m0 < Nn; m0 += 64) {
        __syncthreads();
        #pragma unroll
        for (int i = 0; i < 8; i++) {
            int idx = i * 128 + tid;
            int r = idx >> 4;
            int c4 = (idx & 15) << 2;
            *(float4*)&Ks[r][c4] = *(const float4*)(kbase + (size_t)(m0 + r) * 3 * Cc + c4);
            *(float4*)&Vs[r][c4] = *(const float4*)(vbase + (size_t)(m0 + r) * 3 * Cc + c4);
        }
        __syncthreads();

        #pragma unroll 1
        for (int jc = 0; jc < 64; jc += 16) {
            float s[16];
            #pragma unroll
            for (int j = 0; j < 16; j++) {
                float a0 = 0.f, a1 = 0.f, a2 = 0.f, a3 = 0.f;
                #pragma unroll
                for (int d = 0; d < HDIM; d += 4) {
                    float4 kv = *(const float4*)&Ks[jc + j][d];
                    a0 += q[d + 0] * kv.x;
                    a1 += q[d + 1] * kv.y;
                    a2 += q[d + 2] * kv.z;
                    a3 += q[d + 3] * kv.w;
                }
                s[j] = (a0 + a1) + (a2 + a3);
            }
            float tmax = mmax;
            #pragma unroll
            for (int j = 0; j < 16; j++) tmax = fmaxf(tmax, s[j]);
            const float corr = __expf(mmax - tmax);
            mmax = tmax;
            lsum *= corr;
            #pragma unroll
            for (int d = 0; d < HDIM; d++) o[d] *= corr;
            #pragma unroll
            for (int j = 0; j < 16; j++) {
                const float p = __expf(s[j] - mmax);
                lsum += p;
                #pragma unroll
                for (int d = 0; d < HDIM; d += 4) {
                    float4 vv = *(const float4*)&Vs[jc + j][d];
                    o[d + 0] += p * vv.x;
                    o[d + 1] += p * vv.y;
                    o[d + 2] += p * vv.z;
                    o[d + 3] += p * vv.w;
                }
            }
        }
    }

    const float inv = 1.f / lsum;
    float* optr = att + ((size_t)b * Nn + n) * Cc + h * HDIM;
    #pragma unroll
    for (int d = 0; d < HDIM; d += 4) {
        float4 ov;
        ov.x = o[d + 0] * inv;
        ov.y = o[d + 1] * inv;
        ov.z = o[d + 2] * inv;
        ov.w = o[d + 3] * inv;
        *(float4*)(optr + d) = ov;
    }
}

// ---------------------------------------------------------------------------
extern "C" void kernel_launch(void* const* d_in, const int* in_sizes, int n_in,
                              void* d_out, int out_size)
{
    const float* x      = (const float*)d_in[0];  // [B,N,C]
    const float* w_qkv  = (const float*)d_in[1];  // [C,3C]
    const float* b_qkv  = (const float*)d_in[2];  // [3C]
    const float* w_proj = (const float*)d_in[3];  // [C,C]
    const float* b_proj = (const float*)d_in[4];  // [C]
    float* out = (float*)d_out;                   // [B,N,C]

    float *qkv, *att;
    __nv_bfloat16 *xhi, *xlo, *ahi, *alo, *whi, *wlo, *phi, *plo;
    cudaGetSymbolAddress((void**)&qkv, g_qkv);
    cudaGetSymbolAddress((void**)&att, g_att);
    cudaGetSymbolAddress((void**)&xhi, g_xhi);
    cudaGetSymbolAddress((void**)&xlo, g_xlo);
    cudaGetSymbolAddress((void**)&ahi, g_ahi);
    cudaGetSymbolAddress((void**)&alo, g_alo);
    cudaGetSymbolAddress((void**)&whi, g_whi);
    cudaGetSymbolAddress((void**)&wlo, g_wlo);
    cudaGetSymbolAddress((void**)&phi, g_phi);
    cudaGetSymbolAddress((void**)&plo, g_plo);

    // 1) fp32 -> bf16 hi/lo converts + weight transposes
    {
        const int n4 = MM * KK / 4;   // 1,048,576
        convert_hilo_kernel<<<(n4 + 255) / 256, 256>>>(x, xhi, xlo, n4);
        dim3 blk(32, 8);
        transpose_convert_kernel<<<dim3(NQKV / 32, KK / 32), blk>>>(w_qkv, whi, wlo, KK, NQKV);
        transpose_convert_kernel<<<dim3(NPROJ / 32, KK / 32), blk>>>(w_proj, phi, plo, KK, NPROJ);
    }
    // 2) QKV projection (HMMA): [4096,1024] @ [1024,3072] + b -> g_qkv
    hmma_gemm_kernel<<<dim3(NQKV / 128, MM / 128), 256>>>(
        xhi, xlo, whi, wlo, b_qkv, qkv, NQKV);
    // 3) Attention (fp32, unchanged)
    {
        dim3 grid(Nn / 128, Bb * Hh);
        attn_kernel<<<grid, 128>>>(qkv, att);
    }
    // 4) Convert attention output, then output projection (HMMA)
    {
        const int n4 = MM * KK / 4;
        convert_hilo_kernel<<<(n4 + 255) / 256, 256>>>(att, ahi, alo, n4);
    }
    hmma_gemm_kernel<<<dim3(NPROJ / 128, MM / 128), 256>>>(
        ahi, alo, phi, plo, b_proj, out, NPROJ);
}